// round 14
// baseline (speedup 1.0000x reference)
#include <cuda_runtime.h>
#include <cuda_bf16.h>
#include <math.h>
#include <stdint.h>

// Problem constants
#define B_BATCH 512
#define T_SEQ   256
#define D_IN    512
#define H_DIM   1024

// Fixed-point scales:  h = (H2*128 + H1)/16256,  u = (U2*128 + U1)/65024
#define HSCALE_F 16256.0f
#define USCALE_F 65024.0f

// ---------------------------------------------------------------------------
// Device scratch (static globals — no allocations)
// ---------------------------------------------------------------------------
__device__ __align__(16) signed char g_h2[2][B_BATCH * H_DIM];      // 0.5 MB x2
__device__ __align__(16) signed char g_h1[2][B_BATCH * H_DIM];
__device__ __align__(16) signed char g_U2t[H_DIM * H_DIM];          // 1 MB
__device__ __align__(16) signed char g_U1t[H_DIM * H_DIM];          // 1 MB
__device__ __align__(16) __nv_bfloat16 g_Wt_hi[H_DIM * D_IN];       // 1 MB
__device__ __align__(16) __nv_bfloat16 g_Wt_lo[H_DIM * D_IN];
__device__ __align__(16) float g_xw[(size_t)T_SEQ * B_BATCH * H_DIM]; // 512 MB
__device__ int g_bar[8];   // per-row-group step barriers

// ---------------------------------------------------------------------------
// Helpers (all baseline PTX)
// ---------------------------------------------------------------------------
static __device__ __forceinline__ uint32_t smem_u32(const void* p) {
    uint32_t a;
    asm("{ .reg .u64 t; cvta.to.shared.u64 t, %1; cvt.u32.u64 %0, t; }"
        : "=r"(a) : "l"(p));
    return a;
}
static __device__ __forceinline__ void cp16(uint32_t dst, const void* src) {
    asm volatile("cp.async.cg.shared.global [%0], [%1], 16;" :: "r"(dst), "l"(src));
}
static __device__ __forceinline__ void cp_commit() {
    asm volatile("cp.async.commit_group;" ::: "memory");
}
template <int N> static __device__ __forceinline__ void cp_wait() {
    asm volatile("cp.async.wait_group %0;" :: "n"(N) : "memory");
}
static __device__ __forceinline__ void ldsm4(uint32_t* r, uint32_t a) {
    asm volatile("ldmatrix.sync.aligned.m8n8.x4.shared.b16 {%0,%1,%2,%3}, [%4];"
                 : "=r"(r[0]), "=r"(r[1]), "=r"(r[2]), "=r"(r[3]) : "r"(a));
}
static __device__ __forceinline__ void mma16816(float* d, const uint32_t* a,
                                                uint32_t b0, uint32_t b1) {
    asm volatile(
        "mma.sync.aligned.m16n8k16.row.col.f32.bf16.bf16.f32 "
        "{%0,%1,%2,%3}, {%4,%5,%6,%7}, {%8,%9}, {%0,%1,%2,%3};"
        : "+f"(d[0]), "+f"(d[1]), "+f"(d[2]), "+f"(d[3])
        : "r"(a[0]), "r"(a[1]), "r"(a[2]), "r"(a[3]), "r"(b0), "r"(b1));
}
static __device__ __forceinline__ void mma_s8(int* d, const uint32_t* a,
                                              uint32_t b0, uint32_t b1) {
    asm volatile(
        "mma.sync.aligned.m16n8k32.row.col.s32.s8.s8.s32 "
        "{%0,%1,%2,%3}, {%4,%5,%6,%7}, {%8,%9}, {%0,%1,%2,%3};"
        : "+r"(d[0]), "+r"(d[1]), "+r"(d[2]), "+r"(d[3])
        : "r"(a[0]), "r"(a[1]), "r"(a[2]), "r"(a[3]), "r"(b0), "r"(b1));
}
static __device__ __forceinline__ uint32_t pack2bf(float a, float b) {
    __nv_bfloat16 ha = __float2bfloat16(a), hb = __float2bfloat16(b);
    return (uint32_t)__bfloat16_as_ushort(ha) |
           ((uint32_t)__bfloat16_as_ushort(hb) << 16);
}
// int8 tile swizzle: 64B rows (4x16B units), unit XOR ((row>>1)&3)
#define SWZ8(r, u) ((uint32_t)((r) * 64 + ((((u) ^ (((r) >> 1) & 3))) << 4)))

// ---------------------------------------------------------------------------
// Prep A: transpose + split W (fp32 [512][1024]) -> bf16 hi/lo [1024][512]
// ---------------------------------------------------------------------------
__global__ __launch_bounds__(256) void wt_split_kernel(const float* __restrict__ W)
{
    __shared__ float tile[32][33];
    const int kb = blockIdx.x * 32;
    const int nb = blockIdx.y * 32;
    const int tx = threadIdx.x & 31;
    const int wy = threadIdx.x >> 5;
#pragma unroll
    for (int i = 0; i < 4; i++)
        tile[wy + i * 8][tx] = W[(size_t)(kb + wy + i * 8) * H_DIM + nb + tx];
    __syncthreads();
#pragma unroll
    for (int i = 0; i < 4; i++) {
        const int n = nb + wy + i * 8;
        const float v = tile[tx][wy + i * 8];
        __nv_bfloat16 hi = __float2bfloat16(v);
        __nv_bfloat16 lo = __float2bfloat16(v - __bfloat162float(hi));
        g_Wt_hi[(size_t)n * D_IN + kb + tx] = hi;
        g_Wt_lo[(size_t)n * D_IN + kb + tx] = lo;
    }
}

// ---------------------------------------------------------------------------
// Prep B: transpose + int8 2-limb quantize U (fp32 [1024][1024]) -> [n][k]
// ---------------------------------------------------------------------------
__global__ __launch_bounds__(256) void u_limb_kernel(const float* __restrict__ U)
{
    __shared__ float tile[32][33];
    const int kb = blockIdx.x * 32;
    const int nb = blockIdx.y * 32;
    const int tx = threadIdx.x & 31;
    const int wy = threadIdx.x >> 5;
#pragma unroll
    for (int i = 0; i < 4; i++)
        tile[wy + i * 8][tx] = U[(size_t)(kb + wy + i * 8) * H_DIM + nb + tx];
    __syncthreads();
#pragma unroll
    for (int i = 0; i < 4; i++) {
        const int n = nb + wy + i * 8;
        const float v = tile[tx][wy + i * 8];
        int q2 = __float2int_rn(v * (USCALE_F / 128.0f));   // v * 508
        q2 = max(-127, min(127, q2));
        int q1 = __float2int_rn(v * USCALE_F - 128.0f * (float)q2);
        q1 = max(-127, min(127, q1));
        g_U2t[(size_t)n * H_DIM + kb + tx] = (signed char)q2;
        g_U1t[(size_t)n * H_DIM + kb + tx] = (signed char)q1;
    }
}

__global__ __launch_bounds__(256) void zero_h_kernel() {
    const int i = blockIdx.x * 256 + threadIdx.x;   // < 32768 uint4 per array
    reinterpret_cast<uint4*>(g_h2[0])[i] = make_uint4(0, 0, 0, 0);
    reinterpret_cast<uint4*>(g_h1[0])[i] = make_uint4(0, 0, 0, 0);
    if (blockIdx.x == 0 && threadIdx.x < 8) g_bar[threadIdx.x] = 0;
}

// ---------------------------------------------------------------------------
// Precompute XW[t][b][h] = x[b][t][:] @ W + bias   (split-bf16, 3 passes)
// (verified rounds 7-13 — unchanged)
// ---------------------------------------------------------------------------
#define PA_STR   1040
#define PA_LO    66560
#define PB_OFF   133120
#define PB_STG   10240
#define PSMEM    (PB_OFF + 2 * PB_STG)

__global__ __launch_bounds__(256) void xw_kernel(
    const float* __restrict__ x, const float* __restrict__ bias)
{
    extern __shared__ __align__(16) char ps[];
    const uint32_t sb = smem_u32(ps);
    const int tid  = threadIdx.x;
    const int lane = tid & 31;
    const int wid  = tid >> 5;
    const int wm   = (wid >> 2) * 32;
    const int wn   = (wid & 3) * 16;
    const int row0 = blockIdx.x * 64;

#pragma unroll
    for (int i = 0; i < 32; i++) {
        const int u4 = tid + i * 256;
        const int r  = u4 >> 7, u = u4 & 127;
        const float4 v = *reinterpret_cast<const float4*>(
            &x[(size_t)(row0 + r) * D_IN + u * 4]);
        const float hx = __bfloat162float(__float2bfloat16(v.x));
        const float hy = __bfloat162float(__float2bfloat16(v.y));
        const float hz = __bfloat162float(__float2bfloat16(v.z));
        const float hw = __bfloat162float(__float2bfloat16(v.w));
        *reinterpret_cast<uint2*>(ps + r * PA_STR + u * 8) =
            make_uint2(pack2bf(v.x, v.y), pack2bf(v.z, v.w));
        *reinterpret_cast<uint2*>(ps + PA_LO + r * PA_STR + u * 8) =
            make_uint2(pack2bf(v.x - hx, v.y - hy), pack2bf(v.z - hz, v.w - hw));
    }
    __syncthreads();

    const int crow = tid >> 2, cu = tid & 3;
    const uint32_t bdst  = crow * 80 + cu * 16;
    const uint32_t aoff  = (lane & 15) * PA_STR + (lane >> 4) * 16;
    const uint32_t boff  = (lane & 7) * 80 + (lane >> 3) * 16;

    for (int ng = 0; ng < 16; ng++) {
        const int col0 = ng * 64;
        const __nv_bfloat16* srcBh = g_Wt_hi + (size_t)(col0 + crow) * D_IN + cu * 8;
        const __nv_bfloat16* srcBl = g_Wt_lo + (size_t)(col0 + crow) * D_IN + cu * 8;

        float acc[2][2][4];
#pragma unroll
        for (int a = 0; a < 2; a++)
#pragma unroll
            for (int b = 0; b < 2; b++)
#pragma unroll
                for (int q = 0; q < 4; q++) acc[a][b][q] = 0.0f;

        cp16(sb + PB_OFF + bdst,        srcBh);
        cp16(sb + PB_OFF + 5120 + bdst, srcBl);
        cp_commit();

        for (int c = 0; c < 16; c++) {
            const int s = c & 1;
            if (c + 1 < 16) {
                const uint32_t st = sb + PB_OFF + (s ^ 1) * PB_STG;
                cp16(st + bdst,        srcBh + (c + 1) * 32);
                cp16(st + 5120 + bdst, srcBl + (c + 1) * 32);
                cp_commit();
                cp_wait<1>();
            } else {
                cp_wait<0>();
            }
            __syncthreads();

            const uint32_t stB = sb + PB_OFF + s * PB_STG;
            uint32_t ah[2][2][4], al[2][2][4], bh[2][4], bl[2][4];
#pragma unroll
            for (int mt = 0; mt < 2; mt++)
#pragma unroll
                for (int kt = 0; kt < 2; kt++) {
                    const uint32_t a0 = sb + (wm + mt * 16) * PA_STR
                                      + c * 64 + kt * 32 + aoff;
                    ldsm4(ah[mt][kt], a0);
                    ldsm4(al[mt][kt], a0 + PA_LO);
                }
#pragma unroll
            for (int nt = 0; nt < 2; nt++) {
                const uint32_t b0 = stB + (wn + nt * 8) * 80 + boff;
                ldsm4(bh[nt], b0);
                ldsm4(bl[nt], b0 + 5120);
            }
#pragma unroll
            for (int kt = 0; kt < 2; kt++)
#pragma unroll
                for (int mt = 0; mt < 2; mt++)
#pragma unroll
                    for (int nt = 0; nt < 2; nt++) {
                        mma16816(acc[mt][nt], ah[mt][kt], bh[nt][kt*2], bh[nt][kt*2+1]);
                        mma16816(acc[mt][nt], ah[mt][kt], bl[nt][kt*2], bl[nt][kt*2+1]);
                        mma16816(acc[mt][nt], al[mt][kt], bh[nt][kt*2], bh[nt][kt*2+1]);
                    }
            __syncthreads();
        }

#pragma unroll
        for (int mt = 0; mt < 2; mt++)
#pragma unroll
            for (int nt = 0; nt < 2; nt++) {
                const int cidx = col0 + wn + nt * 8 + (lane & 3) * 2;
                const float bz0 = bias[cidx], bz1 = bias[cidx + 1];
#pragma unroll
                for (int half = 0; half < 2; half++) {
                    const int rg = row0 + wm + mt * 16 + (lane >> 2) + half * 8;
                    const int bb = rg >> 8, tt = rg & 255;
                    float2 o;
                    o.x = acc[mt][nt][half * 2 + 0] + bz0;
                    o.y = acc[mt][nt][half * 2 + 1] + bz1;
                    *reinterpret_cast<float2*>(
                        &g_xw[((size_t)tt * B_BATCH + bb) * H_DIM + cidx]) = o;
                }
            }
    }
}

// ---------------------------------------------------------------------------
// Persistent recurrent kernel v3 — int8 2-limb IMMA.
// U limbs (2x64KB) resident in smem all 256 steps; per-chunk stream = 8KB (H limbs).
// 3 s8 MMAs replace 3 bf16 MMAs at 2x MACs/instr. Grid 128 CTAs, 256 threads.
// ---------------------------------------------------------------------------
#define URES1  65536                     // U1 limb region offset
#define RING0  131072                    // H ring offset
#define RSTG   8192                      // ring stage: H2 4K | H1 4K
#define SMEM_P (RING0 + 4 * RSTG)        // 163840

__global__ __launch_bounds__(256) void rnn_persist_kernel()
{
    extern __shared__ __align__(16) char smem[];
    const uint32_t sb = smem_u32(smem);
    const int tid  = threadIdx.x;
    const int lane = tid & 31;
    const int wid  = tid >> 5;
    const int wm   = (wid >> 2) * 32;      // warp m origin (0/32), covers 32 rows
    const int wn   = (wid & 3) * 16;       // warp n origin
    const int rg   = blockIdx.x >> 4;      // row group 0..7
    const int row0 = rg * 64;
    const int col0 = (blockIdx.x & 15) * 64;

    // ---- stream mapping: 256 threads x 16B per limb per chunk ----
    const int r1 = tid >> 2;               // 0..63
    const int u1 = tid & 3;                // 16B unit in 64B row
    const uint32_t o = SWZ8(r1, u1);

    const signed char* __restrict__ U2s =
        g_U2t + (size_t)(col0 + r1) * H_DIM + u1 * 16;
    const signed char* __restrict__ U1s =
        g_U1t + (size_t)(col0 + r1) * H_DIM + u1 * 16;

    // ---- fragment addressing constants ----
    const int arow = wm + (lane & 15);
    const uint32_t arowb0 = (uint32_t)arow * 64;
    const uint32_t arowb1 = (uint32_t)(arow + 16) * 64;
    const uint32_t asw = (uint32_t)((arow >> 1) & 3);   // same for arow+16
    const int ua_lo = lane >> 4;                        // 0/1
    const int brow = wn + (lane & 7);
    const uint32_t browb0 = (uint32_t)brow * 64;
    const uint32_t browb1 = (uint32_t)(brow + 8) * 64;
    const uint32_t bu = (uint32_t)(((lane >> 3) ^ ((brow >> 1) & 3)) << 4);

    const float R1 = (float)(16384.0 / ((double)HSCALE_F * (double)USCALE_F));
    const float R2 = (float)(128.0 / ((double)HSCALE_F * (double)USCALE_F));

    for (int t = 0; t < T_SEQ; t++) {
        if (t > 0) {
            if (tid == 0) {
                const int target = 16 * t;
                while (*((volatile int*)&g_bar[rg]) < target) { }
            }
            __syncthreads();
            __threadfence();
        }

        const int pin = t & 1;
        const signed char* __restrict__ H2s =
            g_h2[pin] + (size_t)(row0 + r1) * H_DIM + u1 * 16;
        const signed char* __restrict__ H1s =
            g_h1[pin] + (size_t)(row0 + r1) * H_DIM + u1 * 16;

        // prefetch xw for this thread's outputs (consumed in epilogue)
        float2 xwv[2][2][2];
#pragma unroll
        for (int mt = 0; mt < 2; mt++)
#pragma unroll
            for (int nt = 0; nt < 2; nt++) {
                const int cidx = col0 + wn + nt * 8 + (lane & 3) * 2;
#pragma unroll
                for (int h8 = 0; h8 < 2; h8++) {
                    const int r = row0 + wm + mt * 16 + (lane >> 2) + h8 * 8;
                    xwv[mt][nt][h8] = *reinterpret_cast<const float2*>(
                        &g_xw[((size_t)t * B_BATCH + r) * H_DIM + cidx]);
                }
            }

        // one-time: load resident U limbs (16 chunks x 4KB each limb)
        if (t == 0) {
#pragma unroll
            for (int c = 0; c < 16; c++) {
                cp16(sb + c * 4096 + o,         U2s + c * 64);
                cp16(sb + URES1 + c * 4096 + o, U1s + c * 64);
            }
            cp_commit();
        }

        // prologue: H chunks 0..2 into ring stages 0..2
#pragma unroll
        for (int p = 0; p < 3; p++) {
            const uint32_t st = sb + RING0 + p * RSTG;
            cp16(st + o,        H2s + p * 64);
            cp16(st + 4096 + o, H1s + p * 64);
            cp_commit();
        }

        int acc1[2][2][4], acc2[2][2][4];
#pragma unroll
        for (int a = 0; a < 2; a++)
#pragma unroll
            for (int b = 0; b < 2; b++)
#pragma unroll
                for (int q = 0; q < 4; q++) { acc1[a][b][q] = 0; acc2[a][b][q] = 0; }

        for (int c = 0; c < 16; c++) {
            cp_wait<2>();
            __syncthreads();

            if (c + 3 < 16) {   // refill stage (c+3)&3 (its readers are done)
                const uint32_t st = sb + RING0 + ((c + 3) & 3) * RSTG;
                cp16(st + o,        H2s + (c + 3) * 64);
                cp16(st + 4096 + o, H1s + (c + 3) * 64);
            }
            cp_commit();   // empty group at tail keeps wait counts valid

            const uint32_t sA  = sb + RING0 + (c & 3) * RSTG;
            const uint32_t sB2 = sb + c * 4096;
            const uint32_t sB1 = sb + URES1 + c * 4096;

            // B (U limbs) for whole chunk: n8 x k64 per ldsm4
            uint32_t b2[2][4], b1[2][4];
#pragma unroll
            for (int nt = 0; nt < 2; nt++) {
                const uint32_t bro = nt ? browb1 : browb0;
                ldsm4(b2[nt], sB2 + bro + bu);
                ldsm4(b1[nt], sB1 + bro + bu);
            }
#pragma unroll
            for (int ks = 0; ks < 2; ks++) {
                uint32_t a2[2][4], a1[2][4];
                const uint32_t au = (uint32_t)(((ks * 2 + ua_lo) ^ asw) << 4);
#pragma unroll
                for (int mt = 0; mt < 2; mt++) {
                    const uint32_t aro = mt ? arowb1 : arowb0;
                    ldsm4(a2[mt], sA + aro + au);
                    ldsm4(a1[mt], sA + 4096 + aro + au);
                }
#pragma unroll
                for (int mt = 0; mt < 2; mt++)
#pragma unroll
                    for (int nt = 0; nt < 2; nt++) {
                        mma_s8(acc1[mt][nt], a2[mt], b2[nt][ks*2], b2[nt][ks*2+1]);
                        mma_s8(acc2[mt][nt], a2[mt], b1[nt][ks*2], b1[nt][ks*2+1]);
                        mma_s8(acc2[mt][nt], a1[mt], b2[nt][ks*2], b2[nt][ks*2+1]);
                    }
            }
        }

        // epilogue: reconstruct, +XW[t], tanh, re-quantize to limbs, store
        signed char* __restrict__ o2 = g_h2[pin ^ 1];
        signed char* __restrict__ o1 = g_h1[pin ^ 1];
#pragma unroll
        for (int mt = 0; mt < 2; mt++)
#pragma unroll
            for (int nt = 0; nt < 2; nt++) {
                const int cidx = col0 + wn + nt * 8 + (lane & 3) * 2;
#pragma unroll
                for (int h8 = 0; h8 < 2; h8++) {
                    const int r = row0 + wm + mt * 16 + (lane >> 2) + h8 * 8;
                    const float p0 = (float)acc1[mt][nt][h8*2+0] * R1
                                   + (float)acc2[mt][nt][h8*2+0] * R2
                                   + xwv[mt][nt][h8].x;
                    const float p1 = (float)acc1[mt][nt][h8*2+1] * R1
                                   + (float)acc2[mt][nt][h8*2+1] * R2
                                   + xwv[mt][nt][h8].y;
                    const float v0 = tanhf(p0);
                    const float v1 = tanhf(p1);
                    const int q2a = __float2int_rn(v0 * 127.0f);
                    const int q1a = __float2int_rn(v0 * HSCALE_F - 128.0f * (float)q2a);
                    const int q2b = __float2int_rn(v1 * 127.0f);
                    const int q1b = __float2int_rn(v1 * HSCALE_F - 128.0f * (float)q2b);
                    const size_t off = (size_t)r * H_DIM + cidx;
                    *reinterpret_cast<uint16_t*>(&o2[off]) =
                        (uint16_t)(((uint32_t)(uint8_t)(signed char)q2a) |
                                   (((uint32_t)(uint8_t)(signed char)q2b) << 8));
                    *reinterpret_cast<uint16_t*>(&o1[off]) =
                        (uint16_t)(((uint32_t)(uint8_t)(signed char)q1a) |
                                   (((uint32_t)(uint8_t)(signed char)q1b) << 8));
                }
            }

        if (t < T_SEQ - 1) {
            __threadfence();
            __syncthreads();
            if (tid == 0) atomicAdd(&g_bar[rg], 1);
        }
    }
}

// ---------------------------------------------------------------------------
// Final Dense(1): out[b] = h_last[b,:] . Wd + bd  (h from int8 limbs, buf 0)
// ---------------------------------------------------------------------------
__global__ __launch_bounds__(256) void final_dense_kernel(
    const float* __restrict__ Wd, const float* __restrict__ bd,
    float* __restrict__ out)
{
    __shared__ float red[256];
    const int b = blockIdx.x, tid = threadIdx.x;
    const float inv = 1.0f / HSCALE_F;
    float s = 0.0f;
#pragma unroll
    for (int i = tid; i < H_DIM; i += 256) {
        const size_t off = (size_t)b * H_DIM + i;
        const float h = (float)(128 * (int)g_h2[0][off] + (int)g_h1[0][off]) * inv;
        s += h * Wd[i];
    }
    red[tid] = s;
    __syncthreads();
    for (int off = 128; off > 0; off >>= 1) {
        if (tid < off) red[tid] += red[tid + off];
        __syncthreads();
    }
    if (tid == 0) out[b] = red[0] + bd[0];
}

// ---------------------------------------------------------------------------
extern "C" void kernel_launch(void* const* d_in, const int* in_sizes, int n_in,
                              void* d_out, int out_size)
{
    const float* x    = (const float*)d_in[0];   // [512, 256, 512]
    const float* W    = (const float*)d_in[1];   // [512, 1024]
    const float* U    = (const float*)d_in[2];   // [1024, 1024]
    const float* bias = (const float*)d_in[3];   // [1024]
    const float* Wd   = (const float*)d_in[4];   // [1024, 1]
    const float* bd   = (const float*)d_in[5];   // [1]
    float* out        = (float*)d_out;           // [512, 1]

    cudaFuncSetAttribute(xw_kernel,
                         cudaFuncAttributeMaxDynamicSharedMemorySize, PSMEM);
    cudaFuncSetAttribute(rnn_persist_kernel,
                         cudaFuncAttributeMaxDynamicSharedMemorySize, SMEM_P);

    // prep: W split (bf16), U limbs (int8), zero h0 + barriers
    wt_split_kernel<<<dim3(D_IN / 32, H_DIM / 32), 256>>>(W);
    u_limb_kernel<<<dim3(H_DIM / 32, H_DIM / 32), 256>>>(U);
    zero_h_kernel<<<128, 256>>>();

    // XW = x @ W + b  (one big parallel tensor GEMM)
    xw_kernel<<<(B_BATCH * T_SEQ) / 64, 256, PSMEM>>>(x, bias);

    // all 256 recurrent steps in ONE persistent launch (int8 IMMA)
    rnn_persist_kernel<<<128, 256, SMEM_P>>>();

    final_dense_kernel<<<B_BATCH, 256>>>(Wd, bd, out);
}

// round 15
// speedup vs baseline: 1.0004x; 1.0004x over previous
#include <cuda_runtime.h>
#include <cuda_bf16.h>
#include <math.h>
#include <stdint.h>

// Problem constants
#define B_BATCH 512
#define T_SEQ   256
#define D_IN    512
#define H_DIM   1024

// Fixed-point scales:  h = (H2*128 + H1)/16256,  u = (U2*128 + U1)/65024
#define HSCALE_F 16256.0f
#define USCALE_F 65024.0f

// ---------------------------------------------------------------------------
// Device scratch (static globals — no allocations)
// ---------------------------------------------------------------------------
__device__ __align__(16) signed char g_h2[2][B_BATCH * H_DIM];      // 0.5 MB x2
__device__ __align__(16) signed char g_h1[2][B_BATCH * H_DIM];
__device__ __align__(16) signed char g_U2t[H_DIM * H_DIM];          // 1 MB
__device__ __align__(16) signed char g_U1t[H_DIM * H_DIM];          // 1 MB
__device__ __align__(16) __nv_bfloat16 g_Wt_hi[H_DIM * D_IN];       // 1 MB
__device__ __align__(16) __nv_bfloat16 g_Wt_lo[H_DIM * D_IN];
__device__ __align__(16) float g_xw[(size_t)T_SEQ * B_BATCH * H_DIM]; // 512 MB
__device__ int g_bar[8];   // per-row-group step barriers

// ---------------------------------------------------------------------------
// Helpers (all baseline PTX)
// ---------------------------------------------------------------------------
static __device__ __forceinline__ uint32_t smem_u32(const void* p) {
    uint32_t a;
    asm("{ .reg .u64 t; cvta.to.shared.u64 t, %1; cvt.u32.u64 %0, t; }"
        : "=r"(a) : "l"(p));
    return a;
}
static __device__ __forceinline__ void cp16(uint32_t dst, const void* src) {
    asm volatile("cp.async.cg.shared.global [%0], [%1], 16;" :: "r"(dst), "l"(src));
}
static __device__ __forceinline__ void cp_commit() {
    asm volatile("cp.async.commit_group;" ::: "memory");
}
template <int N> static __device__ __forceinline__ void cp_wait() {
    asm volatile("cp.async.wait_group %0;" :: "n"(N) : "memory");
}
static __device__ __forceinline__ void ldsm4(uint32_t* r, uint32_t a) {
    asm volatile("ldmatrix.sync.aligned.m8n8.x4.shared.b16 {%0,%1,%2,%3}, [%4];"
                 : "=r"(r[0]), "=r"(r[1]), "=r"(r[2]), "=r"(r[3]) : "r"(a));
}
static __device__ __forceinline__ void mma16816(float* d, const uint32_t* a,
                                                uint32_t b0, uint32_t b1) {
    asm volatile(
        "mma.sync.aligned.m16n8k16.row.col.f32.bf16.bf16.f32 "
        "{%0,%1,%2,%3}, {%4,%5,%6,%7}, {%8,%9}, {%0,%1,%2,%3};"
        : "+f"(d[0]), "+f"(d[1]), "+f"(d[2]), "+f"(d[3])
        : "r"(a[0]), "r"(a[1]), "r"(a[2]), "r"(a[3]), "r"(b0), "r"(b1));
}
static __device__ __forceinline__ void mma_s8(int* d, const uint32_t* a,
                                              uint32_t b0, uint32_t b1) {
    asm volatile(
        "mma.sync.aligned.m16n8k32.row.col.s32.s8.s8.s32 "
        "{%0,%1,%2,%3}, {%4,%5,%6,%7}, {%8,%9}, {%0,%1,%2,%3};"
        : "+r"(d[0]), "+r"(d[1]), "+r"(d[2]), "+r"(d[3])
        : "r"(a[0]), "r"(a[1]), "r"(a[2]), "r"(a[3]), "r"(b0), "r"(b1));
}
static __device__ __forceinline__ uint32_t pack2bf(float a, float b) {
    __nv_bfloat16 ha = __float2bfloat16(a), hb = __float2bfloat16(b);
    return (uint32_t)__bfloat16_as_ushort(ha) |
           ((uint32_t)__bfloat16_as_ushort(hb) << 16);
}
// int8 tile swizzle: 64B rows (4x16B units), unit XOR ((row>>1)&3)
#define SWZ8(r, u) ((uint32_t)((r) * 64 + ((((u) ^ (((r) >> 1) & 3))) << 4)))

// ---------------------------------------------------------------------------
// Prep A: transpose + split W (fp32 [512][1024]) -> bf16 hi/lo [1024][512]
// ---------------------------------------------------------------------------
__global__ __launch_bounds__(256) void wt_split_kernel(const float* __restrict__ W)
{
    __shared__ float tile[32][33];
    const int kb = blockIdx.x * 32;
    const int nb = blockIdx.y * 32;
    const int tx = threadIdx.x & 31;
    const int wy = threadIdx.x >> 5;
#pragma unroll
    for (int i = 0; i < 4; i++)
        tile[wy + i * 8][tx] = W[(size_t)(kb + wy + i * 8) * H_DIM + nb + tx];
    __syncthreads();
#pragma unroll
    for (int i = 0; i < 4; i++) {
        const int n = nb + wy + i * 8;
        const float v = tile[tx][wy + i * 8];
        __nv_bfloat16 hi = __float2bfloat16(v);
        __nv_bfloat16 lo = __float2bfloat16(v - __bfloat162float(hi));
        g_Wt_hi[(size_t)n * D_IN + kb + tx] = hi;
        g_Wt_lo[(size_t)n * D_IN + kb + tx] = lo;
    }
}

// ---------------------------------------------------------------------------
// Prep B: transpose + int8 2-limb quantize U (fp32 [1024][1024]) -> [n][k]
// ---------------------------------------------------------------------------
__global__ __launch_bounds__(256) void u_limb_kernel(const float* __restrict__ U)
{
    __shared__ float tile[32][33];
    const int kb = blockIdx.x * 32;
    const int nb = blockIdx.y * 32;
    const int tx = threadIdx.x & 31;
    const int wy = threadIdx.x >> 5;
#pragma unroll
    for (int i = 0; i < 4; i++)
        tile[wy + i * 8][tx] = U[(size_t)(kb + wy + i * 8) * H_DIM + nb + tx];
    __syncthreads();
#pragma unroll
    for (int i = 0; i < 4; i++) {
        const int n = nb + wy + i * 8;
        const float v = tile[tx][wy + i * 8];
        int q2 = __float2int_rn(v * (USCALE_F / 128.0f));   // v * 508
        q2 = max(-127, min(127, q2));
        int q1 = __float2int_rn(v * USCALE_F - 128.0f * (float)q2);
        q1 = max(-127, min(127, q1));
        g_U2t[(size_t)n * H_DIM + kb + tx] = (signed char)q2;
        g_U1t[(size_t)n * H_DIM + kb + tx] = (signed char)q1;
    }
}

__global__ __launch_bounds__(256) void zero_h_kernel() {
    const int i = blockIdx.x * 256 + threadIdx.x;   // < 32768 uint4 per array
    reinterpret_cast<uint4*>(g_h2[0])[i] = make_uint4(0, 0, 0, 0);
    reinterpret_cast<uint4*>(g_h1[0])[i] = make_uint4(0, 0, 0, 0);
    if (blockIdx.x == 0 && threadIdx.x < 8) g_bar[threadIdx.x] = 0;
}

// ---------------------------------------------------------------------------
// Precompute XW[t][b][h] = x[b][t][:] @ W + bias   (split-bf16, 3 passes)
// (verified rounds 7-13 — unchanged)
// ---------------------------------------------------------------------------
#define PA_STR   1040
#define PA_LO    66560
#define PB_OFF   133120
#define PB_STG   10240
#define PSMEM    (PB_OFF + 2 * PB_STG)

__global__ __launch_bounds__(256) void xw_kernel(
    const float* __restrict__ x, const float* __restrict__ bias)
{
    extern __shared__ __align__(16) char ps[];
    const uint32_t sb = smem_u32(ps);
    const int tid  = threadIdx.x;
    const int lane = tid & 31;
    const int wid  = tid >> 5;
    const int wm   = (wid >> 2) * 32;
    const int wn   = (wid & 3) * 16;
    const int row0 = blockIdx.x * 64;

#pragma unroll
    for (int i = 0; i < 32; i++) {
        const int u4 = tid + i * 256;
        const int r  = u4 >> 7, u = u4 & 127;
        const float4 v = *reinterpret_cast<const float4*>(
            &x[(size_t)(row0 + r) * D_IN + u * 4]);
        const float hx = __bfloat162float(__float2bfloat16(v.x));
        const float hy = __bfloat162float(__float2bfloat16(v.y));
        const float hz = __bfloat162float(__float2bfloat16(v.z));
        const float hw = __bfloat162float(__float2bfloat16(v.w));
        *reinterpret_cast<uint2*>(ps + r * PA_STR + u * 8) =
            make_uint2(pack2bf(v.x, v.y), pack2bf(v.z, v.w));
        *reinterpret_cast<uint2*>(ps + PA_LO + r * PA_STR + u * 8) =
            make_uint2(pack2bf(v.x - hx, v.y - hy), pack2bf(v.z - hz, v.w - hw));
    }
    __syncthreads();

    const int crow = tid >> 2, cu = tid & 3;
    const uint32_t bdst  = crow * 80 + cu * 16;
    const uint32_t aoff  = (lane & 15) * PA_STR + (lane >> 4) * 16;
    const uint32_t boff  = (lane & 7) * 80 + (lane >> 3) * 16;

    for (int ng = 0; ng < 16; ng++) {
        const int col0 = ng * 64;
        const __nv_bfloat16* srcBh = g_Wt_hi + (size_t)(col0 + crow) * D_IN + cu * 8;
        const __nv_bfloat16* srcBl = g_Wt_lo + (size_t)(col0 + crow) * D_IN + cu * 8;

        float acc[2][2][4];
#pragma unroll
        for (int a = 0; a < 2; a++)
#pragma unroll
            for (int b = 0; b < 2; b++)
#pragma unroll
                for (int q = 0; q < 4; q++) acc[a][b][q] = 0.0f;

        cp16(sb + PB_OFF + bdst,        srcBh);
        cp16(sb + PB_OFF + 5120 + bdst, srcBl);
        cp_commit();

        for (int c = 0; c < 16; c++) {
            const int s = c & 1;
            if (c + 1 < 16) {
                const uint32_t st = sb + PB_OFF + (s ^ 1) * PB_STG;
                cp16(st + bdst,        srcBh + (c + 1) * 32);
                cp16(st + 5120 + bdst, srcBl + (c + 1) * 32);
                cp_commit();
                cp_wait<1>();
            } else {
                cp_wait<0>();
            }
            __syncthreads();

            const uint32_t stB = sb + PB_OFF + s * PB_STG;
            uint32_t ah[2][2][4], al[2][2][4], bh[2][4], bl[2][4];
#pragma unroll
            for (int mt = 0; mt < 2; mt++)
#pragma unroll
                for (int kt = 0; kt < 2; kt++) {
                    const uint32_t a0 = sb + (wm + mt * 16) * PA_STR
                                      + c * 64 + kt * 32 + aoff;
                    ldsm4(ah[mt][kt], a0);
                    ldsm4(al[mt][kt], a0 + PA_LO);
                }
#pragma unroll
            for (int nt = 0; nt < 2; nt++) {
                const uint32_t b0 = stB + (wn + nt * 8) * 80 + boff;
                ldsm4(bh[nt], b0);
                ldsm4(bl[nt], b0 + 5120);
            }
#pragma unroll
            for (int kt = 0; kt < 2; kt++)
#pragma unroll
                for (int mt = 0; mt < 2; mt++)
#pragma unroll
                    for (int nt = 0; nt < 2; nt++) {
                        mma16816(acc[mt][nt], ah[mt][kt], bh[nt][kt*2], bh[nt][kt*2+1]);
                        mma16816(acc[mt][nt], ah[mt][kt], bl[nt][kt*2], bl[nt][kt*2+1]);
                        mma16816(acc[mt][nt], al[mt][kt], bh[nt][kt*2], bh[nt][kt*2+1]);
                    }
            __syncthreads();
        }

#pragma unroll
        for (int mt = 0; mt < 2; mt++)
#pragma unroll
            for (int nt = 0; nt < 2; nt++) {
                const int cidx = col0 + wn + nt * 8 + (lane & 3) * 2;
                const float bz0 = bias[cidx], bz1 = bias[cidx + 1];
#pragma unroll
                for (int half = 0; half < 2; half++) {
                    const int rg = row0 + wm + mt * 16 + (lane >> 2) + half * 8;
                    const int bb = rg >> 8, tt = rg & 255;
                    float2 o;
                    o.x = acc[mt][nt][half * 2 + 0] + bz0;
                    o.y = acc[mt][nt][half * 2 + 1] + bz1;
                    *reinterpret_cast<float2*>(
                        &g_xw[((size_t)tt * B_BATCH + bb) * H_DIM + cidx]) = o;
                }
            }
    }
}

// ---------------------------------------------------------------------------
// Persistent recurrent kernel v3 — int8 2-limb IMMA.
// U limbs (2x64KB) resident in smem all 256 steps; per-chunk stream = 8KB (H limbs).
// 3 s8 MMAs replace 3 bf16 MMAs at 2x MACs/instr. Grid 128 CTAs, 256 threads.
// ---------------------------------------------------------------------------
#define URES1  65536                     // U1 limb region offset
#define RING0  131072                    // H ring offset
#define RSTG   8192                      // ring stage: H2 4K | H1 4K
#define SMEM_P (RING0 + 4 * RSTG)        // 163840

__global__ __launch_bounds__(256) void rnn_persist_kernel()
{
    extern __shared__ __align__(16) char smem[];
    const uint32_t sb = smem_u32(smem);
    const int tid  = threadIdx.x;
    const int lane = tid & 31;
    const int wid  = tid >> 5;
    const int wm   = (wid >> 2) * 32;      // warp m origin (0/32), covers 32 rows
    const int wn   = (wid & 3) * 16;       // warp n origin
    const int rg   = blockIdx.x >> 4;      // row group 0..7
    const int row0 = rg * 64;
    const int col0 = (blockIdx.x & 15) * 64;

    // ---- stream mapping: 256 threads x 16B per limb per chunk ----
    const int r1 = tid >> 2;               // 0..63
    const int u1 = tid & 3;                // 16B unit in 64B row
    const uint32_t o = SWZ8(r1, u1);

    const signed char* __restrict__ U2s =
        g_U2t + (size_t)(col0 + r1) * H_DIM + u1 * 16;
    const signed char* __restrict__ U1s =
        g_U1t + (size_t)(col0 + r1) * H_DIM + u1 * 16;

    // ---- fragment addressing constants ----
    const int arow = wm + (lane & 15);
    const uint32_t arowb0 = (uint32_t)arow * 64;
    const uint32_t arowb1 = (uint32_t)(arow + 16) * 64;
    const uint32_t asw = (uint32_t)((arow >> 1) & 3);   // same for arow+16
    const int ua_lo = lane >> 4;                        // 0/1
    const int brow = wn + (lane & 7);
    const uint32_t browb0 = (uint32_t)brow * 64;
    const uint32_t browb1 = (uint32_t)(brow + 8) * 64;
    const uint32_t bu = (uint32_t)(((lane >> 3) ^ ((brow >> 1) & 3)) << 4);

    const float R1 = (float)(16384.0 / ((double)HSCALE_F * (double)USCALE_F));
    const float R2 = (float)(128.0 / ((double)HSCALE_F * (double)USCALE_F));

    for (int t = 0; t < T_SEQ; t++) {
        if (t > 0) {
            if (tid == 0) {
                const int target = 16 * t;
                while (*((volatile int*)&g_bar[rg]) < target) { }
            }
            __syncthreads();
            __threadfence();
        }

        const int pin = t & 1;
        const signed char* __restrict__ H2s =
            g_h2[pin] + (size_t)(row0 + r1) * H_DIM + u1 * 16;
        const signed char* __restrict__ H1s =
            g_h1[pin] + (size_t)(row0 + r1) * H_DIM + u1 * 16;

        // prefetch xw for this thread's outputs (consumed in epilogue)
        float2 xwv[2][2][2];
#pragma unroll
        for (int mt = 0; mt < 2; mt++)
#pragma unroll
            for (int nt = 0; nt < 2; nt++) {
                const int cidx = col0 + wn + nt * 8 + (lane & 3) * 2;
#pragma unroll
                for (int h8 = 0; h8 < 2; h8++) {
                    const int r = row0 + wm + mt * 16 + (lane >> 2) + h8 * 8;
                    xwv[mt][nt][h8] = *reinterpret_cast<const float2*>(
                        &g_xw[((size_t)t * B_BATCH + r) * H_DIM + cidx]);
                }
            }

        // one-time: load resident U limbs (16 chunks x 4KB each limb)
        if (t == 0) {
#pragma unroll
            for (int c = 0; c < 16; c++) {
                cp16(sb + c * 4096 + o,         U2s + c * 64);
                cp16(sb + URES1 + c * 4096 + o, U1s + c * 64);
            }
            cp_commit();
        }

        // prologue: H chunks 0..2 into ring stages 0..2
#pragma unroll
        for (int p = 0; p < 3; p++) {
            const uint32_t st = sb + RING0 + p * RSTG;
            cp16(st + o,        H2s + p * 64);
            cp16(st + 4096 + o, H1s + p * 64);
            cp_commit();
        }

        int acc1[2][2][4], acc2[2][2][4];
#pragma unroll
        for (int a = 0; a < 2; a++)
#pragma unroll
            for (int b = 0; b < 2; b++)
#pragma unroll
                for (int q = 0; q < 4; q++) { acc1[a][b][q] = 0; acc2[a][b][q] = 0; }

        for (int c = 0; c < 16; c++) {
            cp_wait<2>();
            __syncthreads();

            if (c + 3 < 16) {   // refill stage (c+3)&3 (its readers are done)
                const uint32_t st = sb + RING0 + ((c + 3) & 3) * RSTG;
                cp16(st + o,        H2s + (c + 3) * 64);
                cp16(st + 4096 + o, H1s + (c + 3) * 64);
            }
            cp_commit();   // empty group at tail keeps wait counts valid

            const uint32_t sA  = sb + RING0 + (c & 3) * RSTG;
            const uint32_t sB2 = sb + c * 4096;
            const uint32_t sB1 = sb + URES1 + c * 4096;

            // B (U limbs) for whole chunk: n8 x k64 per ldsm4
            uint32_t b2[2][4], b1[2][4];
#pragma unroll
            for (int nt = 0; nt < 2; nt++) {
                const uint32_t bro = nt ? browb1 : browb0;
                ldsm4(b2[nt], sB2 + bro + bu);
                ldsm4(b1[nt], sB1 + bro + bu);
            }
#pragma unroll
            for (int ks = 0; ks < 2; ks++) {
                uint32_t a2[2][4], a1[2][4];
                const uint32_t au = (uint32_t)(((ks * 2 + ua_lo) ^ asw) << 4);
#pragma unroll
                for (int mt = 0; mt < 2; mt++) {
                    const uint32_t aro = mt ? arowb1 : arowb0;
                    ldsm4(a2[mt], sA + aro + au);
                    ldsm4(a1[mt], sA + 4096 + aro + au);
                }
#pragma unroll
                for (int mt = 0; mt < 2; mt++)
#pragma unroll
                    for (int nt = 0; nt < 2; nt++) {
                        mma_s8(acc1[mt][nt], a2[mt], b2[nt][ks*2], b2[nt][ks*2+1]);
                        mma_s8(acc2[mt][nt], a2[mt], b1[nt][ks*2], b1[nt][ks*2+1]);
                        mma_s8(acc2[mt][nt], a1[mt], b2[nt][ks*2], b2[nt][ks*2+1]);
                    }
            }
        }

        // epilogue: reconstruct, +XW[t], tanh, re-quantize to limbs, store
        signed char* __restrict__ o2 = g_h2[pin ^ 1];
        signed char* __restrict__ o1 = g_h1[pin ^ 1];
#pragma unroll
        for (int mt = 0; mt < 2; mt++)
#pragma unroll
            for (int nt = 0; nt < 2; nt++) {
                const int cidx = col0 + wn + nt * 8 + (lane & 3) * 2;
#pragma unroll
                for (int h8 = 0; h8 < 2; h8++) {
                    const int r = row0 + wm + mt * 16 + (lane >> 2) + h8 * 8;
                    const float p0 = (float)acc1[mt][nt][h8*2+0] * R1
                                   + (float)acc2[mt][nt][h8*2+0] * R2
                                   + xwv[mt][nt][h8].x;
                    const float p1 = (float)acc1[mt][nt][h8*2+1] * R1
                                   + (float)acc2[mt][nt][h8*2+1] * R2
                                   + xwv[mt][nt][h8].y;
                    const float v0 = tanhf(p0);
                    const float v1 = tanhf(p1);
                    const int q2a = __float2int_rn(v0 * 127.0f);
                    const int q1a = __float2int_rn(v0 * HSCALE_F - 128.0f * (float)q2a);
                    const int q2b = __float2int_rn(v1 * 127.0f);
                    const int q1b = __float2int_rn(v1 * HSCALE_F - 128.0f * (float)q2b);
                    const size_t off = (size_t)r * H_DIM + cidx;
                    *reinterpret_cast<uint16_t*>(&o2[off]) =
                        (uint16_t)(((uint32_t)(uint8_t)(signed char)q2a) |
                                   (((uint32_t)(uint8_t)(signed char)q2b) << 8));
                    *reinterpret_cast<uint16_t*>(&o1[off]) =
                        (uint16_t)(((uint32_t)(uint8_t)(signed char)q1a) |
                                   (((uint32_t)(uint8_t)(signed char)q1b) << 8));
                }
            }

        if (t < T_SEQ - 1) {
            __threadfence();
            __syncthreads();
            if (tid == 0) atomicAdd(&g_bar[rg], 1);
        }
    }
}

// ---------------------------------------------------------------------------
// Final Dense(1): out[b] = h_last[b,:] . Wd + bd  (h from int8 limbs, buf 0)
// ---------------------------------------------------------------------------
__global__ __launch_bounds__(256) void final_dense_kernel(
    const float* __restrict__ Wd, const float* __restrict__ bd,
    float* __restrict__ out)
{
    __shared__ float red[256];
    const int b = blockIdx.x, tid = threadIdx.x;
    const float inv = 1.0f / HSCALE_F;
    float s = 0.0f;
#pragma unroll
    for (int i = tid; i < H_DIM; i += 256) {
        const size_t off = (size_t)b * H_DIM + i;
        const float h = (float)(128 * (int)g_h2[0][off] + (int)g_h1[0][off]) * inv;
        s += h * Wd[i];
    }
    red[tid] = s;
    __syncthreads();
    for (int off = 128; off > 0; off >>= 1) {
        if (tid < off) red[tid] += red[tid + off];
        __syncthreads();
    }
    if (tid == 0) out[b] = red[0] + bd[0];
}

// ---------------------------------------------------------------------------
extern "C" void kernel_launch(void* const* d_in, const int* in_sizes, int n_in,
                              void* d_out, int out_size)
{
    const float* x    = (const float*)d_in[0];   // [512, 256, 512]
    const float* W    = (const float*)d_in[1];   // [512, 1024]
    const float* U    = (const float*)d_in[2];   // [1024, 1024]
    const float* bias = (const float*)d_in[3];   // [1024]
    const float* Wd   = (const float*)d_in[4];   // [1024, 1]
    const float* bd   = (const float*)d_in[5];   // [1]
    float* out        = (float*)d_out;           // [512, 1]

    cudaFuncSetAttribute(xw_kernel,
                         cudaFuncAttributeMaxDynamicSharedMemorySize, PSMEM);
    cudaFuncSetAttribute(rnn_persist_kernel,
                         cudaFuncAttributeMaxDynamicSharedMemorySize, SMEM_P);

    // prep: W split (bf16), U limbs (int8), zero h0 + barriers
    wt_split_kernel<<<dim3(D_IN / 32, H_DIM / 32), 256>>>(W);
    u_limb_kernel<<<dim3(H_DIM / 32, H_DIM / 32), 256>>>(U);
    zero_h_kernel<<<128, 256>>>();

    // XW = x @ W + b  (one big parallel tensor GEMM)
    xw_kernel<<<(B_BATCH * T_SEQ) / 64, 256, PSMEM>>>(x, bias);

    // all 256 recurrent steps in ONE persistent launch (int8 IMMA)
    rnn_persist_kernel<<<128, 256, SMEM_P>>>();

    final_dense_kernel<<<B_BATCH, 256>>>(Wd, bd, out);
}

// round 17
// speedup vs baseline: 2.1623x; 2.1614x over previous
#include <cuda_runtime.h>
#include <cuda_fp16.h>
#include <math.h>
#include <stdint.h>

// Problem constants
#define B_BATCH 512
#define T_SEQ   256
#define D_IN    512
#define H_DIM   1024

#define LO_SCALE   2048.0f
#define INV_LO     (1.0f / 2048.0f)

// ---------------------------------------------------------------------------
// Device scratch (static globals — no allocations)
// ---------------------------------------------------------------------------
__device__ __align__(16) __half g_hh[2][B_BATCH * H_DIM];    // h hi limb, 1MB x2
__device__ __align__(16) __half g_hl[2][B_BATCH * H_DIM];    // h lo limb (x2048)
__device__ __align__(16) __half g_Uth[H_DIM * H_DIM];        // U^T fp16, 2 MB
__device__ __align__(16) __half g_Wth[H_DIM * D_IN];         // W^T fp16, 1 MB
__device__ __align__(16) float g_xw[(size_t)T_SEQ * B_BATCH * H_DIM]; // 512 MB
__device__ int g_bar[8];   // per-row-group step barriers

// ---------------------------------------------------------------------------
// Helpers (all baseline PTX)
// ---------------------------------------------------------------------------
static __device__ __forceinline__ uint32_t smem_u32(const void* p) {
    uint32_t a;
    asm("{ .reg .u64 t; cvta.to.shared.u64 t, %1; cvt.u32.u64 %0, t; }"
        : "=r"(a) : "l"(p));
    return a;
}
static __device__ __forceinline__ void cp16(uint32_t dst, const void* src) {
    asm volatile("cp.async.cg.shared.global [%0], [%1], 16;" :: "r"(dst), "l"(src));
}
static __device__ __forceinline__ void cp_commit() {
    asm volatile("cp.async.commit_group;" ::: "memory");
}
template <int N> static __device__ __forceinline__ void cp_wait() {
    asm volatile("cp.async.wait_group %0;" :: "n"(N) : "memory");
}
static __device__ __forceinline__ void ldsm4(uint32_t* r, uint32_t a) {
    asm volatile("ldmatrix.sync.aligned.m8n8.x4.shared.b16 {%0,%1,%2,%3}, [%4];"
                 : "=r"(r[0]), "=r"(r[1]), "=r"(r[2]), "=r"(r[3]) : "r"(a));
}
// fp16 inputs, fp32 accumulate
static __device__ __forceinline__ void mma_f16(float* d, const uint32_t* a,
                                               uint32_t b0, uint32_t b1) {
    asm volatile(
        "mma.sync.aligned.m16n8k16.row.col.f32.f16.f16.f32 "
        "{%0,%1,%2,%3}, {%4,%5,%6,%7}, {%8,%9}, {%0,%1,%2,%3};"
        : "+f"(d[0]), "+f"(d[1]), "+f"(d[2]), "+f"(d[3])
        : "r"(a[0]), "r"(a[1]), "r"(a[2]), "r"(a[3]), "r"(b0), "r"(b1));
}
static __device__ __forceinline__ uint32_t pack2h(float a, float b) {
    __half ha = __float2half_rn(a), hb = __float2half_rn(b);
    return (uint32_t)__half_as_ushort(ha) |
           ((uint32_t)__half_as_ushort(hb) << 16);
}
// pad-free 16B-unit swizzle: 128B rows (8x16B units), unit XOR (row&7)
#define SWZ(row, col) ((uint32_t)((row) * 128 + (((col) ^ ((row) & 7)) << 4)))

// ---------------------------------------------------------------------------
// Prep: transpose fp32 weight [K][1024] -> fp16 [1024][K]
// which: 0 -> W (K=512) into g_Wth, 1 -> U (K=1024) into g_Uth
// ---------------------------------------------------------------------------
__global__ __launch_bounds__(256) void transpose_h_kernel(
    const float* __restrict__ src, int K, int which)
{
    __shared__ float tile[32][33];
    __half* dst = which ? g_Uth : g_Wth;
    const int kb = blockIdx.x * 32;
    const int nb = blockIdx.y * 32;
    const int tx = threadIdx.x & 31;
    const int wy = threadIdx.x >> 5;
#pragma unroll
    for (int i = 0; i < 4; i++)
        tile[wy + i * 8][tx] = src[(size_t)(kb + wy + i * 8) * H_DIM + nb + tx];
    __syncthreads();
#pragma unroll
    for (int i = 0; i < 4; i++) {
        const int n = nb + wy + i * 8;
        dst[(size_t)n * K + kb + tx] = __float2half_rn(tile[tx][wy + i * 8]);
    }
}

__global__ __launch_bounds__(256) void zero_h_kernel() {
    const int i = blockIdx.x * 256 + threadIdx.x;   // 65536 uint4 per array
    reinterpret_cast<uint4*>(g_hh[0])[i] = make_uint4(0, 0, 0, 0);
    reinterpret_cast<uint4*>(g_hl[0])[i] = make_uint4(0, 0, 0, 0);
    if (blockIdx.x == 0 && threadIdx.x < 8) g_bar[threadIdx.x] = 0;
}

// ---------------------------------------------------------------------------
// Precompute XW[t][b][h] = x[b][t][:] @ W + bias   (2-pass fp16 split)
// x 2-limb fp16 (lo scaled x2048), W single fp16. 2048 CTAs, 256 threads.
// CTA keeps its 64-row A slice (hi+lo, 128KB) in smem; streams W per n-group.
// ---------------------------------------------------------------------------
#define PA_STR   1040                      // 512 fp16 (1024B) + 16B pad
#define PA_LO    66560                     // 64 * 1040
#define PB_OFF   133120                    // A region total (hi+lo)
#define PB_STG   5120                      // B stage: 64 rows x 80B
#define PSMEM    (PB_OFF + 2 * PB_STG)     // 143360

__global__ __launch_bounds__(256) void xw_kernel(
    const float* __restrict__ x, const float* __restrict__ bias)
{
    extern __shared__ __align__(16) char ps[];
    const uint32_t sb = smem_u32(ps);
    const int tid  = threadIdx.x;
    const int lane = tid & 31;
    const int wid  = tid >> 5;
    const int wm   = (wid >> 2) * 32;
    const int wn   = (wid & 3) * 16;
    const int row0 = blockIdx.x * 64;

    // ---- phase 1: load 64 x-rows (fp32), split into fp16 hi / lo*2048 ----
#pragma unroll
    for (int i = 0; i < 32; i++) {
        const int u4 = tid + i * 256;
        const int r  = u4 >> 7, u = u4 & 127;
        const float4 v = *reinterpret_cast<const float4*>(
            &x[(size_t)(row0 + r) * D_IN + u * 4]);
        const float hx = __half2float(__float2half_rn(v.x));
        const float hy = __half2float(__float2half_rn(v.y));
        const float hz = __half2float(__float2half_rn(v.z));
        const float hw = __half2float(__float2half_rn(v.w));
        *reinterpret_cast<uint2*>(ps + r * PA_STR + u * 8) =
            make_uint2(pack2h(v.x, v.y), pack2h(v.z, v.w));
        *reinterpret_cast<uint2*>(ps + PA_LO + r * PA_STR + u * 8) =
            make_uint2(pack2h((v.x - hx) * LO_SCALE, (v.y - hy) * LO_SCALE),
                       pack2h((v.z - hz) * LO_SCALE, (v.w - hw) * LO_SCALE));
    }
    __syncthreads();

    const int crow = tid >> 2, cu = tid & 3;
    const uint32_t bdst  = crow * 80 + cu * 16;
    const uint32_t aoff  = (lane & 15) * PA_STR + (lane >> 4) * 16;
    const uint32_t boff  = (lane & 7) * 80 + (lane >> 3) * 16;

    for (int ng = 0; ng < 16; ng++) {
        const int col0 = ng * 64;
        const __half* srcB = g_Wth + (size_t)(col0 + crow) * D_IN + cu * 8;

        float acc1[2][2][4], acc2[2][2][4];
#pragma unroll
        for (int a = 0; a < 2; a++)
#pragma unroll
            for (int b = 0; b < 2; b++)
#pragma unroll
                for (int q = 0; q < 4; q++) { acc1[a][b][q] = 0.0f; acc2[a][b][q] = 0.0f; }

        cp16(sb + PB_OFF + bdst, srcB);
        cp_commit();

        for (int c = 0; c < 16; c++) {
            const int s = c & 1;
            if (c + 1 < 16) {
                cp16(sb + PB_OFF + (s ^ 1) * PB_STG + bdst, srcB + (c + 1) * 32);
                cp_commit();
                cp_wait<1>();
            } else {
                cp_wait<0>();
            }
            __syncthreads();

            const uint32_t stB = sb + PB_OFF + s * PB_STG;
            uint32_t ah[2][2][4], al[2][2][4], bw[2][4];
#pragma unroll
            for (int mt = 0; mt < 2; mt++)
#pragma unroll
                for (int kt = 0; kt < 2; kt++) {
                    const uint32_t a0 = sb + (wm + mt * 16) * PA_STR
                                      + c * 64 + kt * 32 + aoff;
                    ldsm4(ah[mt][kt], a0);
                    ldsm4(al[mt][kt], a0 + PA_LO);
                }
#pragma unroll
            for (int nt = 0; nt < 2; nt++)
                ldsm4(bw[nt], stB + (wn + nt * 8) * 80 + boff);
#pragma unroll
            for (int kt = 0; kt < 2; kt++)
#pragma unroll
                for (int mt = 0; mt < 2; mt++)
#pragma unroll
                    for (int nt = 0; nt < 2; nt++) {
                        mma_f16(acc1[mt][nt], ah[mt][kt], bw[nt][kt*2], bw[nt][kt*2+1]);
                        mma_f16(acc2[mt][nt], al[mt][kt], bw[nt][kt*2], bw[nt][kt*2+1]);
                    }
            __syncthreads();
        }

        // epilogue: XW = acc1 + acc2/2048 + bias   (row = b*256 + t)
#pragma unroll
        for (int mt = 0; mt < 2; mt++)
#pragma unroll
            for (int nt = 0; nt < 2; nt++) {
                const int cidx = col0 + wn + nt * 8 + (lane & 3) * 2;
                const float bz0 = bias[cidx], bz1 = bias[cidx + 1];
#pragma unroll
                for (int half = 0; half < 2; half++) {
                    const int rg = row0 + wm + mt * 16 + (lane >> 2) + half * 8;
                    const int bb = rg >> 8, tt = rg & 255;
                    float2 o;
                    o.x = acc1[mt][nt][half*2+0] + acc2[mt][nt][half*2+0] * INV_LO + bz0;
                    o.y = acc1[mt][nt][half*2+1] + acc2[mt][nt][half*2+1] * INV_LO + bz1;
                    *reinterpret_cast<float2*>(
                        &g_xw[((size_t)tt * B_BATCH + bb) * H_DIM + cidx]) = o;
                }
            }
    }
}

// ---------------------------------------------------------------------------
// Persistent recurrent kernel v4 — 2-pass fp16.
// U^T fp16 (128KB) resident in smem all 256 steps; per-chunk stream = 16KB
// (h hi + lo limbs). 2 HMMA passes share the same B fragments.
// Grid 128 CTAs (bx>>4 = row group, bx&15 = col group), 256 threads.
// ---------------------------------------------------------------------------
#define RING0  131072                     // h ring offset (after resident U)
#define RSTG   16384                      // ring stage: A_hi 8K | A_lo 8K
#define SMEM_P (RING0 + 4 * RSTG)         // 196608

__global__ __launch_bounds__(256) void rnn_persist_kernel()
{
    extern __shared__ __align__(16) char smem[];
    const uint32_t sb = smem_u32(smem);
    const int tid  = threadIdx.x;
    const int lane = tid & 31;
    const int wid  = tid >> 5;
    const int wm   = (wid >> 2) * 32;      // 2 m-positions (0,32)
    const int wn   = (wid & 3) * 16;       // 4 n-positions
    const int rg   = blockIdx.x >> 4;      // row group 0..7
    const int row0 = rg * 64;
    const int col0 = (blockIdx.x & 15) * 64;

    // ---- stream mapping: 2 x 16B units per tensor per chunk per thread ----
    const int r1 = tid >> 3;               // rows r1 and r1+32
    const int c1 = tid & 7;                // 16B unit in 128B row
    const uint32_t o1 = SWZ(r1, c1);
    const uint32_t o2 = SWZ(r1 + 32, c1);

    const __half* __restrict__ U1 = g_Uth + (size_t)(col0 + r1) * H_DIM + c1 * 8;
    const __half* __restrict__ U2 = U1 + (size_t)32 * H_DIM;

    // ---- fragment addressing constants (proven v2 pattern) ----
    const int arow = wm + (lane & 15);
    const uint32_t arowt0 = (uint32_t)arow * 128;
    const uint32_t arowt1 = (uint32_t)(arow + 16) * 128;
    const uint32_t swa = (uint32_t)(arow & 7);
    const int ua_lo = lane >> 4;                   // 0/1
    const uint32_t browt0 = (uint32_t)(wn + (lane & 7)) * 128;
    const uint32_t browt1 = (uint32_t)(wn + 8 + (lane & 7)) * 128;
    const uint32_t swb = (uint32_t)(lane & 7);
    const int ub_lo = lane >> 3;                   // 0..3

    for (int t = 0; t < T_SEQ; t++) {
        if (t > 0) {
            if (tid == 0) {
                const int target = 16 * t;
                while (*((volatile int*)&g_bar[rg]) < target) { }
            }
            __syncthreads();
            __threadfence();
        }

        const int pin = t & 1;
        const __half* __restrict__ Ah1 =
            g_hh[pin] + (size_t)(row0 + r1) * H_DIM + c1 * 8;
        const __half* __restrict__ Ah2 = Ah1 + (size_t)32 * H_DIM;
        const __half* __restrict__ Al1 =
            g_hl[pin] + (size_t)(row0 + r1) * H_DIM + c1 * 8;
        const __half* __restrict__ Al2 = Al1 + (size_t)32 * H_DIM;

        // prefetch xw for this thread's outputs
        float2 xwv[2][2][2];
#pragma unroll
        for (int mt = 0; mt < 2; mt++)
#pragma unroll
            for (int nt = 0; nt < 2; nt++) {
                const int cidx = col0 + wn + nt * 8 + (lane & 3) * 2;
#pragma unroll
                for (int h8 = 0; h8 < 2; h8++) {
                    const int r = row0 + wm + mt * 16 + (lane >> 2) + h8 * 8;
                    xwv[mt][nt][h8] = *reinterpret_cast<const float2*>(
                        &g_xw[((size_t)t * B_BATCH + r) * H_DIM + cidx]);
                }
            }

        // one-time: load resident U^T (16 chunks x 8KB)
        if (t == 0) {
#pragma unroll
            for (int c = 0; c < 16; c++) {
                cp16(sb + c * 8192 + o1, U1 + c * 64);
                cp16(sb + c * 8192 + o2, U2 + c * 64);
            }
            cp_commit();
        }

        // prologue: h chunks 0..2 into ring stages 0..2
#pragma unroll
        for (int p = 0; p < 3; p++) {
            const uint32_t st = sb + RING0 + p * RSTG;
            const int kb = p * 64;
            cp16(st + o1,        Ah1 + kb);
            cp16(st + o2,        Ah2 + kb);
            cp16(st + 8192 + o1, Al1 + kb);
            cp16(st + 8192 + o2, Al2 + kb);
            cp_commit();
        }

        float acc1[2][2][4], acc2[2][2][4];
#pragma unroll
        for (int a = 0; a < 2; a++)
#pragma unroll
            for (int b = 0; b < 2; b++)
#pragma unroll
                for (int q = 0; q < 4; q++) { acc1[a][b][q] = 0.0f; acc2[a][b][q] = 0.0f; }

        for (int c = 0; c < 16; c++) {
            cp_wait<2>();
            __syncthreads();

            if (c + 3 < 16) {   // refill stage (c+3)&3 (its readers are done)
                const uint32_t st = sb + RING0 + ((c + 3) & 3) * RSTG;
                const int kb = (c + 3) * 64;
                cp16(st + o1,        Ah1 + kb);
                cp16(st + o2,        Ah2 + kb);
                cp16(st + 8192 + o1, Al1 + kb);
                cp16(st + 8192 + o2, Al2 + kb);
            }
            cp_commit();   // empty group at tail keeps wait counts valid

            const uint32_t sA = sb + RING0 + (c & 3) * RSTG;
            const uint32_t sB = sb + c * 8192;

#pragma unroll
            for (int kb2 = 0; kb2 < 2; kb2++) {
                uint32_t bw[2][4];
                const uint32_t ub = (uint32_t)(kb2 * 4 + ub_lo);
#pragma unroll
                for (int nt = 0; nt < 2; nt++) {
                    const uint32_t bro = nt ? browt1 : browt0;
                    ldsm4(bw[nt], sB + bro + ((ub ^ swb) << 4));
                }
#pragma unroll
                for (int hf = 0; hf < 2; hf++) {
                    uint32_t ah[2][4], al[2][4];
                    const uint32_t ua = (uint32_t)(kb2 * 4 + hf * 2 + ua_lo);
                    const uint32_t au = (ua ^ swa) << 4;
#pragma unroll
                    for (int mt = 0; mt < 2; mt++) {
                        const uint32_t aro = mt ? arowt1 : arowt0;
                        ldsm4(ah[mt], sA + aro + au);
                        ldsm4(al[mt], sA + 8192 + aro + au);
                    }
#pragma unroll
                    for (int mt = 0; mt < 2; mt++)
#pragma unroll
                        for (int nt = 0; nt < 2; nt++) {
                            mma_f16(acc1[mt][nt], ah[mt],
                                    bw[nt][hf * 2], bw[nt][hf * 2 + 1]);
                            mma_f16(acc2[mt][nt], al[mt],
                                    bw[nt][hf * 2], bw[nt][hf * 2 + 1]);
                        }
                }
            }
        }

        // epilogue: pre = acc1 + acc2/2048 + XW[t]; tanh; split to fp16 limbs
        __half* __restrict__ oh = g_hh[pin ^ 1];
        __half* __restrict__ ol = g_hl[pin ^ 1];
#pragma unroll
        for (int mt = 0; mt < 2; mt++)
#pragma unroll
            for (int nt = 0; nt < 2; nt++) {
                const int cidx = col0 + wn + nt * 8 + (lane & 3) * 2;
#pragma unroll
                for (int h8 = 0; h8 < 2; h8++) {
                    const int r = row0 + wm + mt * 16 + (lane >> 2) + h8 * 8;
                    const float v0 = tanhf(acc1[mt][nt][h8*2+0]
                                         + acc2[mt][nt][h8*2+0] * INV_LO
                                         + xwv[mt][nt][h8].x);
                    const float v1 = tanhf(acc1[mt][nt][h8*2+1]
                                         + acc2[mt][nt][h8*2+1] * INV_LO
                                         + xwv[mt][nt][h8].y);
                    const float q0 = __half2float(__float2half_rn(v0));
                    const float q1 = __half2float(__float2half_rn(v1));
                    const size_t off = (size_t)r * H_DIM + cidx;
                    *reinterpret_cast<uint32_t*>(&oh[off]) = pack2h(v0, v1);
                    *reinterpret_cast<uint32_t*>(&ol[off]) =
                        pack2h((v0 - q0) * LO_SCALE, (v1 - q1) * LO_SCALE);
                }
            }

        if (t < T_SEQ - 1) {
            __threadfence();
            __syncthreads();
            if (tid == 0) atomicAdd(&g_bar[rg], 1);
        }
    }
}

// ---------------------------------------------------------------------------
// Final Dense(1): out[b] = h_last[b,:] . Wd + bd  (h = hi + lo/2048, buf 0)
// ---------------------------------------------------------------------------
__global__ __launch_bounds__(256) void final_dense_kernel(
    const float* __restrict__ Wd, const float* __restrict__ bd,
    float* __restrict__ out)
{
    __shared__ float red[256];
    const int b = blockIdx.x, tid = threadIdx.x;
    float s = 0.0f;
#pragma unroll
    for (int i = tid; i < H_DIM; i += 256) {
        const size_t off = (size_t)b * H_DIM + i;
        const float h = __half2float(g_hh[0][off])
                      + __half2float(g_hl[0][off]) * INV_LO;
        s += h * Wd[i];
    }
    red[tid] = s;
    __syncthreads();
    for (int off = 128; off > 0; off >>= 1) {
        if (tid < off) red[tid] += red[tid + off];
        __syncthreads();
    }
    if (tid == 0) out[b] = red[0] + bd[0];
}

// ---------------------------------------------------------------------------
extern "C" void kernel_launch(void* const* d_in, const int* in_sizes, int n_in,
                              void* d_out, int out_size)
{
    const float* x    = (const float*)d_in[0];   // [512, 256, 512]
    const float* W    = (const float*)d_in[1];   // [512, 1024]
    const float* U    = (const float*)d_in[2];   // [1024, 1024]
    const float* bias = (const float*)d_in[3];   // [1024]
    const float* Wd   = (const float*)d_in[4];   // [1024, 1]
    const float* bd   = (const float*)d_in[5];   // [1]
    float* out        = (float*)d_out;           // [512, 1]

    cudaFuncSetAttribute(xw_kernel,
                         cudaFuncAttributeMaxDynamicSharedMemorySize, PSMEM);
    cudaFuncSetAttribute(rnn_persist_kernel,
                         cudaFuncAttributeMaxDynamicSharedMemorySize, SMEM_P);

    // prep: fp16 transposed weights, zero h0 + barriers
    transpose_h_kernel<<<dim3(D_IN / 32, H_DIM / 32), 256>>>(W, D_IN, 0);
    transpose_h_kernel<<<dim3(H_DIM / 32, H_DIM / 32), 256>>>(U, H_DIM, 1);
    zero_h_kernel<<<256, 256>>>();

    // XW = x @ W + b  (one big parallel fp16 2-pass GEMM)
    xw_kernel<<<(B_BATCH * T_SEQ) / 64, 256, PSMEM>>>(x, bias);

    // all 256 recurrent steps in ONE persistent launch (fp16 2-pass)
    rnn_persist_kernel<<<128, 256, SMEM_P>>>();

    final_dense_kernel<<<B_BATCH, 256>>>(Wd, bd, out);
}